// round 3
// baseline (speedup 1.0000x reference)
#include <cuda_runtime.h>
#include <math.h>

// Problem constants (B=1, H=16, L=1024, D=64)
#define NSEQ 16
#define LSEQ 1024
#define DIM  64
#define D2   128          // feature dim = 2*DIM
#define CHK  64           // chunk length
#define NC   (LSEQ/CHK)   // 16 chunks per sequence

// Scratch: per-(seq,chunk) KV sums [D2][DIM] and k-sums [D2]
__device__ float g_kv[NSEQ * NC * D2 * DIM];    // 8 MB
__device__ float g_ksum[NSEQ * NC * D2];        // 128 KB

// ---------------------------------------------------------------------------
// Kernel 1: per-chunk sums.  grid = NSEQ*NC blocks, 256 threads.
// smem: ks[64][128] (feature-mapped k), vs[64][64]
// ---------------------------------------------------------------------------
__global__ void k_chunksum(const float* __restrict__ kg_,
                           const float* __restrict__ vg_) {
    extern __shared__ float sm[];
    float* ks = sm;                 // [CHK][128]
    float* vs = sm + CHK * 128;     // [CHK][64]

    const int s = blockIdx.x >> 4;
    const int c = blockIdx.x & 15;
    const int t = threadIdx.x;

    const float* kg = kg_ + (size_t)(s * LSEQ + c * CHK) * DIM;
    const float* vg = vg_ + (size_t)(s * LSEQ + c * CHK) * DIM;

    // Load chunk of k (with relu + sin/cos feature map) and v into smem.
    for (int i = t; i < CHK * DIM / 4; i += 256) {      // 1024 float4
        int j = i >> 4;
        int d = (i & 15) * 4;
        float4 kv4 = reinterpret_cast<const float4*>(kg)[i];
        float4 vv4 = reinterpret_cast<const float4*>(vg)[i];
        int gl = c * CHK + j;
        float w = 1.5707963267948966f * (float)(gl + 1) * (1.0f / (float)LSEQ);
        float sw, cw;
        sincosf(w, &sw, &cw);
        float kx = fmaxf(kv4.x, 0.f), ky = fmaxf(kv4.y, 0.f);
        float kz = fmaxf(kv4.z, 0.f), kw = fmaxf(kv4.w, 0.f);
        float* kr = ks + j * 128 + d;
        kr[0] = kx * sw; kr[1] = ky * sw; kr[2] = kz * sw; kr[3] = kw * sw;
        kr[64] = kx * cw; kr[65] = ky * cw; kr[66] = kz * cw; kr[67] = kw * cw;
        *reinterpret_cast<float4*>(vs + j * DIM + d) = vv4;
    }
    __syncthreads();

    // Accumulate KV[d2][dv] += ks[j][d2] * vs[j][dv]. Tile: 8 d2 x 4 dv.
    const int dvg = t & 15;        // dv base = 4*dvg
    const int d2g = t >> 4;        // d2 base = 8*d2g
    float acc[8][4];
#pragma unroll
    for (int i = 0; i < 8; i++)
#pragma unroll
        for (int j = 0; j < 4; j++) acc[i][j] = 0.f;

    for (int j = 0; j < CHK; j++) {
        float4 ka = *reinterpret_cast<float4*>(ks + j * 128 + 8 * d2g);
        float4 kb = *reinterpret_cast<float4*>(ks + j * 128 + 8 * d2g + 4);
        float4 vv = *reinterpret_cast<float4*>(vs + j * DIM + 4 * dvg);
        float k8[8] = {ka.x, ka.y, ka.z, ka.w, kb.x, kb.y, kb.z, kb.w};
        float v4[4] = {vv.x, vv.y, vv.z, vv.w};
#pragma unroll
        for (int i = 0; i < 8; i++)
#pragma unroll
            for (int jj = 0; jj < 4; jj++) acc[i][jj] += k8[i] * v4[jj];
    }

    // Store KV chunk sum.
    float* outp = g_kv + ((size_t)(s * NC + c) * D2 + 8 * d2g) * DIM + 4 * dvg;
#pragma unroll
    for (int i = 0; i < 8; i++) {
        float4 o = make_float4(acc[i][0], acc[i][1], acc[i][2], acc[i][3]);
        *reinterpret_cast<float4*>(outp + i * DIM) = o;
    }

    // k-sum per feature dim.
    if (t < D2) {
        float ssum = 0.f;
        for (int j = 0; j < CHK; j++) ssum += ks[j * 128 + t];
        g_ksum[(size_t)(s * NC + c) * D2 + t] = ssum;
    }
}

// ---------------------------------------------------------------------------
// Kernel 2: in-place exclusive prefix scan over chunks (elementwise parallel).
// grid covers NSEQ*D2*DIM threads.
// ---------------------------------------------------------------------------
__global__ void k_scan() {
    const int tid = blockIdx.x * blockDim.x + threadIdx.x;
    const int stride = D2 * DIM;
    if (tid < NSEQ * stride) {
        int s = tid / stride;
        int e = tid % stride;
        float* base = g_kv + (size_t)s * NC * stride + e;
        float tmp[NC];
#pragma unroll
        for (int c = 0; c < NC; c++) tmp[c] = base[(size_t)c * stride];
        float run = 0.f;
#pragma unroll
        for (int c = 0; c < NC; c++) {
            base[(size_t)c * stride] = run;
            run += tmp[c];
        }
    }
    if (tid < NSEQ * D2) {
        int s = tid / D2;
        int e = tid % D2;
        float* b2 = g_ksum + (size_t)s * NC * D2 + e;
        float tmp[NC];
#pragma unroll
        for (int c = 0; c < NC; c++) tmp[c] = b2[c * D2];
        float run = 0.f;
#pragma unroll
        for (int c = 0; c < NC; c++) {
            b2[c * D2] = run;
            run += tmp[c];
        }
    }
}

// ---------------------------------------------------------------------------
// Kernel 3: per-chunk output. grid = NSEQ*NC blocks, 256 threads.
// smem layout (floats):
//   q_s [64][129]   (stride 129 to break bank conflicts)
//   k_s [64][129]   (reused as s0[128][64] after phase A)
//   v_s [64][64]
//   A_s [64][65]
//   ksum_s[128], denom_s[64]
// ---------------------------------------------------------------------------
#define QS_STRIDE 129
#define AS_STRIDE 65
#define SM3_FLOATS (64*QS_STRIDE + 64*QS_STRIDE + 64*64 + 64*AS_STRIDE + 128 + 64)

__global__ void k_output(const float* __restrict__ qg_,
                         const float* __restrict__ kg_,
                         const float* __restrict__ vg_,
                         float* __restrict__ outg) {
    extern __shared__ float sm[];
    float* q_s    = sm;
    float* k_s    = q_s + 64 * QS_STRIDE;
    float* v_s    = k_s + 64 * QS_STRIDE;
    float* A_s    = v_s + 64 * 64;
    float* ksum_s = A_s + 64 * AS_STRIDE;
    float* den_s  = ksum_s + 128;

    const int s = blockIdx.x >> 4;
    const int c = blockIdx.x & 15;
    const int t = threadIdx.x;

    const float* qg = qg_ + (size_t)(s * LSEQ + c * CHK) * DIM;
    const float* kg = kg_ + (size_t)(s * LSEQ + c * CHK) * DIM;
    const float* vg = vg_ + (size_t)(s * LSEQ + c * CHK) * DIM;

    for (int i = t; i < CHK * DIM / 4; i += 256) {
        int j = i >> 4;
        int d = (i & 15) * 4;
        float4 q4 = reinterpret_cast<const float4*>(qg)[i];
        float4 k4 = reinterpret_cast<const float4*>(kg)[i];
        float4 v4 = reinterpret_cast<const float4*>(vg)[i];
        int gl = c * CHK + j;
        float w = 1.5707963267948966f * (float)(gl + 1) * (1.0f / (float)LSEQ);
        float sw, cw;
        sincosf(w, &sw, &cw);
        float qx = fmaxf(q4.x, 0.f), qy = fmaxf(q4.y, 0.f);
        float qz = fmaxf(q4.z, 0.f), qw = fmaxf(q4.w, 0.f);
        float kx = fmaxf(k4.x, 0.f), ky = fmaxf(k4.y, 0.f);
        float kz = fmaxf(k4.z, 0.f), kw = fmaxf(k4.w, 0.f);
        float* qr = q_s + j * QS_STRIDE + d;
        qr[0] = qx * sw; qr[1] = qy * sw; qr[2] = qz * sw; qr[3] = qw * sw;
        qr[64] = qx * cw; qr[65] = qy * cw; qr[66] = qz * cw; qr[67] = qw * cw;
        float* kr = k_s + j * QS_STRIDE + d;
        kr[0] = kx * sw; kr[1] = ky * sw; kr[2] = kz * sw; kr[3] = kw * sw;
        kr[64] = kx * cw; kr[65] = ky * cw; kr[66] = kz * cw; kr[67] = kw * cw;
        *reinterpret_cast<float4*>(v_s + j * DIM + d) = v4;
    }
    if (t < D2) ksum_s[t] = g_ksum[(size_t)(s * NC + c) * D2 + t];
    __syncthreads();

    // Phase A: A[l][j] = dot(q_[l], k_[j]) over 128 dims. Tile 4l x 4j.
    const int ti = t >> 4;     // l base = 4*ti
    const int tj = t & 15;     // j base = 4*tj
    {
        float accA[4][4];
#pragma unroll
        for (int i = 0; i < 4; i++)
#pragma unroll
            for (int j = 0; j < 4; j++) accA[i][j] = 0.f;

        for (int kk = 0; kk < D2; kk++) {
            float rq[4], rk[4];
#pragma unroll
            for (int i = 0; i < 4; i++) rq[i] = q_s[(4 * ti + i) * QS_STRIDE + kk];
#pragma unroll
            for (int j = 0; j < 4; j++) rk[j] = k_s[(4 * tj + j) * QS_STRIDE + kk];
#pragma unroll
            for (int i = 0; i < 4; i++)
#pragma unroll
                for (int j = 0; j < 4; j++) accA[i][j] += rq[i] * rk[j];
        }
        // Write causally-masked A.
#pragma unroll
        for (int i = 0; i < 4; i++)
#pragma unroll
            for (int j = 0; j < 4; j++) {
                int l = 4 * ti + i, jc = 4 * tj + j;
                A_s[l * AS_STRIDE + jc] = (jc <= l) ? accA[i][j] : 0.f;
            }
    }
    __syncthreads();

    // Load exclusive-prefix S0 into k_s region (now free): s0[kk][d], stride 64.
    float* s0 = k_s;
    {
        const float* kvg = g_kv + (size_t)(s * NC + c) * D2 * DIM;
        for (int i = t; i < D2 * DIM / 4; i += 256)
            reinterpret_cast<float4*>(s0)[i] =
                reinterpret_cast<const float4*>(kvg)[i];
    }
    // Denominators (uses A_s, q_s, ksum_s — independent of s0 region).
    if (t < CHK) {
        int l = t;
        float d1 = 0.f;
        for (int kk = 0; kk < D2; kk++) d1 += q_s[l * QS_STRIDE + kk] * ksum_s[kk];
        float d2v = 0.f;
        for (int jc = 0; jc <= l; jc++) d2v += A_s[l * AS_STRIDE + jc];
        den_s[l] = fmaxf(d1 + d2v, 1e-6f);
    }
    __syncthreads();

    // Phase B: out[l][d] = q_[l]·S0[:,d] + sum_j A_masked[l][j]*v[j][d]
    float accO[4][4];
#pragma unroll
    for (int i = 0; i < 4; i++)
#pragma unroll
        for (int j = 0; j < 4; j++) accO[i][j] = 0.f;

    for (int kk = 0; kk < D2; kk++) {
        float rq[4];
#pragma unroll
        for (int i = 0; i < 4; i++) rq[i] = q_s[(4 * ti + i) * QS_STRIDE + kk];
        float4 rs = *reinterpret_cast<float4*>(s0 + kk * DIM + 4 * tj);
        float s4[4] = {rs.x, rs.y, rs.z, rs.w};
#pragma unroll
        for (int i = 0; i < 4; i++)
#pragma unroll
            for (int j = 0; j < 4; j++) accO[i][j] += rq[i] * s4[j];
    }
    for (int jc = 0; jc < CHK; jc++) {
        float ra[4];
#pragma unroll
        for (int i = 0; i < 4; i++) ra[i] = A_s[(4 * ti + i) * AS_STRIDE + jc];
        float4 rv = *reinterpret_cast<float4*>(v_s + jc * DIM + 4 * tj);
        float v4[4] = {rv.x, rv.y, rv.z, rv.w};
#pragma unroll
        for (int i = 0; i < 4; i++)
#pragma unroll
            for (int j = 0; j < 4; j++) accO[i][j] += ra[i] * v4[j];
    }

    // Epilogue: divide by denom and store.
#pragma unroll
    for (int i = 0; i < 4; i++) {
        int l = 4 * ti + i;
        float inv = 1.0f / den_s[l];
        float4 o = make_float4(accO[i][0] * inv, accO[i][1] * inv,
                               accO[i][2] * inv, accO[i][3] * inv);
        *reinterpret_cast<float4*>(
            outg + (size_t)((s * LSEQ + c * CHK + l) * DIM) + 4 * tj) = o;
    }
}

// ---------------------------------------------------------------------------
extern "C" void kernel_launch(void* const* d_in, const int* in_sizes, int n_in,
                              void* d_out, int out_size) {
    const float* q = (const float*)d_in[0];
    const float* k = (const float*)d_in[1];
    const float* v = (const float*)d_in[2];
    float* out = (float*)d_out;

    static bool attr_set = false;
    if (!attr_set) {
        cudaFuncSetAttribute(k_chunksum,
                             cudaFuncAttributeMaxDynamicSharedMemorySize,
                             (CHK * 128 + CHK * DIM) * sizeof(float));
        cudaFuncSetAttribute(k_output,
                             cudaFuncAttributeMaxDynamicSharedMemorySize,
                             SM3_FLOATS * sizeof(float));
        attr_set = true;
    }

    size_t sm1 = (CHK * 128 + CHK * DIM) * sizeof(float);   // 48 KB
    size_t sm3 = SM3_FLOATS * sizeof(float);                // ~97.5 KB

    k_chunksum<<<NSEQ * NC, 256, sm1>>>(k, v);
    int scan_threads = NSEQ * D2 * DIM;                     // 131072
    k_scan<<<(scan_threads + 255) / 256, 256>>>();
    k_output<<<NSEQ * NC, 256, sm3>>>(q, k, v, out);
}

// round 4
// speedup vs baseline: 1.6946x; 1.6946x over previous
#include <cuda_runtime.h>
#include <math.h>
#include <stdint.h>

// Problem constants (B=1, H=16, L=1024, D=64)
#define NSEQ 16
#define LSEQ 1024
#define DIM  64
#define D2   128          // feature dim = 2*DIM
#define CHK  64           // chunk length
#define NC   (LSEQ/CHK)   // 16 chunks per sequence

// Scratch: per-(seq,chunk) KV sums [D2][DIM] and k-sums [D2]
__device__ float g_kv[NSEQ * NC * D2 * DIM];    // 8 MB
__device__ float g_ksum[NSEQ * NC * D2];        // 128 KB

// ---------------------------------------------------------------------------
// tf32 helpers
// ---------------------------------------------------------------------------
__device__ __forceinline__ float f2tf(float x) {
    uint32_t r;
    asm("cvt.rna.tf32.f32 %0, %1;" : "=r"(r) : "f"(x));
    return __uint_as_float(r);
}

__device__ __forceinline__ void mma_tf32(float d[4],
                                         const uint32_t a[4],
                                         const uint32_t b[2],
                                         const float c[4]) {
    asm volatile(
        "mma.sync.aligned.m16n8k8.row.col.f32.tf32.tf32.f32 "
        "{%0,%1,%2,%3}, {%4,%5,%6,%7}, {%8,%9}, {%10,%11,%12,%13};\n"
        : "=f"(d[0]), "=f"(d[1]), "=f"(d[2]), "=f"(d[3])
        : "r"(a[0]), "r"(a[1]), "r"(a[2]), "r"(a[3]),
          "r"(b[0]), "r"(b[1]),
          "f"(c[0]), "f"(c[1]), "f"(c[2]), "f"(c[3]));
}

#define BITS(x) __float_as_uint(x)

// ---------------------------------------------------------------------------
// Kernel 1: per-chunk KV sums via tensor cores.
// grid = NSEQ*NC, 256 threads (8 warps).
// GEMM: C[128(d2) x 64(dv)] = k~^T @ v over K=64 positions.
// smem: ks[64][136] (k~ tf32, [j][d2]), vs[64][72] (v tf32, [j][dv])
// Strides: 136 % 32 == 8 (A-style access conflict-free),
//          72  % 32 == 8 (B-style access conflict-free).
// ---------------------------------------------------------------------------
#define K1_KS 136
#define K1_VS 72
#define K1_SMEM ((CHK*K1_KS + CHK*K1_VS) * sizeof(float))

__global__ void k_chunksum(const float* __restrict__ kg_,
                           const float* __restrict__ vg_) {
    extern __shared__ float sm[];
    float* ks = sm;                   // [64][136]
    float* vs = sm + CHK * K1_KS;     // [64][72]

    const int s = blockIdx.x >> 4;
    const int c = blockIdx.x & 15;
    const int t = threadIdx.x;

    const float* kg = kg_ + (size_t)(s * LSEQ + c * CHK) * DIM;
    const float* vg = vg_ + (size_t)(s * LSEQ + c * CHK) * DIM;

    // Load + feature-map k, load v; tf32-round everything.
    for (int i = t; i < CHK * DIM / 4; i += 256) {
        int j = i >> 4;
        int d = (i & 15) * 4;
        float4 k4 = reinterpret_cast<const float4*>(kg)[i];
        float4 v4 = reinterpret_cast<const float4*>(vg)[i];
        int gl = c * CHK + j;
        float w = 1.5707963267948966f * (float)(gl + 1) * (1.0f / (float)LSEQ);
        float sw, cw;
        sincosf(w, &sw, &cw);
        float kx = fmaxf(k4.x, 0.f), ky = fmaxf(k4.y, 0.f);
        float kz = fmaxf(k4.z, 0.f), kw = fmaxf(k4.w, 0.f);
        float4 kss = make_float4(f2tf(kx * sw), f2tf(ky * sw),
                                 f2tf(kz * sw), f2tf(kw * sw));
        float4 ksc = make_float4(f2tf(kx * cw), f2tf(ky * cw),
                                 f2tf(kz * cw), f2tf(kw * cw));
        *reinterpret_cast<float4*>(ks + j * K1_KS + d)       = kss;
        *reinterpret_cast<float4*>(ks + j * K1_KS + 64 + d)  = ksc;
        float4 vt = make_float4(f2tf(v4.x), f2tf(v4.y), f2tf(v4.z), f2tf(v4.w));
        *reinterpret_cast<float4*>(vs + j * K1_VS + d) = vt;
    }
    __syncthreads();

    const int wid  = t >> 5;
    const int lane = t & 31;
    const int g    = lane >> 2;       // group id (0..7)
    const int tig  = lane & 3;        // thread in group (0..3)
    const int warpM = (wid >> 1) * 32;   // 0,32,64,96
    const int warpN = (wid & 1) * 32;    // 0,32

    float acc[2][4][4];
#pragma unroll
    for (int mt = 0; mt < 2; mt++)
#pragma unroll
        for (int nt = 0; nt < 4; nt++)
#pragma unroll
            for (int cc = 0; cc < 4; cc++) acc[mt][nt][cc] = 0.f;

#pragma unroll
    for (int kk = 0; kk < 8; kk++) {
        const int k0 = kk * 8;
        uint32_t af[2][4];
#pragma unroll
        for (int mt = 0; mt < 2; mt++) {
            int mb = warpM + mt * 16 + g;
            af[mt][0] = BITS(ks[(k0 + tig)     * K1_KS + mb]);
            af[mt][1] = BITS(ks[(k0 + tig)     * K1_KS + mb + 8]);
            af[mt][2] = BITS(ks[(k0 + tig + 4) * K1_KS + mb]);
            af[mt][3] = BITS(ks[(k0 + tig + 4) * K1_KS + mb + 8]);
        }
        uint32_t bf[4][2];
#pragma unroll
        for (int nt = 0; nt < 4; nt++) {
            int nb = warpN + nt * 8 + g;
            bf[nt][0] = BITS(vs[(k0 + tig)     * K1_VS + nb]);
            bf[nt][1] = BITS(vs[(k0 + tig + 4) * K1_VS + nb]);
        }
#pragma unroll
        for (int mt = 0; mt < 2; mt++)
#pragma unroll
            for (int nt = 0; nt < 4; nt++)
                mma_tf32(acc[mt][nt], af[mt], bf[nt], acc[mt][nt]);
    }

    // Store chunk KV sum.
    float* outp = g_kv + (size_t)(s * NC + c) * D2 * DIM;
#pragma unroll
    for (int mt = 0; mt < 2; mt++)
#pragma unroll
        for (int nt = 0; nt < 4; nt++) {
            int m0 = warpM + mt * 16 + g;
            int n0 = warpN + nt * 8 + 2 * tig;
            *reinterpret_cast<float2*>(outp + m0 * DIM + n0) =
                make_float2(acc[mt][nt][0], acc[mt][nt][1]);
            *reinterpret_cast<float2*>(outp + (m0 + 8) * DIM + n0) =
                make_float2(acc[mt][nt][2], acc[mt][nt][3]);
        }

    // k-sum per feature dim.
    if (t < D2) {
        float ssum = 0.f;
        for (int j = 0; j < CHK; j++) ssum += ks[j * K1_KS + t];
        g_ksum[(size_t)(s * NC + c) * D2 + t] = ssum;
    }
}

// ---------------------------------------------------------------------------
// Kernel 2: in-place exclusive prefix scan over chunks (elementwise parallel).
// ---------------------------------------------------------------------------
__global__ void k_scan() {
    const int tid = blockIdx.x * blockDim.x + threadIdx.x;
    const int stride = D2 * DIM;
    if (tid < NSEQ * stride) {
        int s = tid / stride;
        int e = tid % stride;
        float* base = g_kv + (size_t)s * NC * stride + e;
        float tmp[NC];
#pragma unroll
        for (int c = 0; c < NC; c++) tmp[c] = base[(size_t)c * stride];
        float run = 0.f;
#pragma unroll
        for (int c = 0; c < NC; c++) {
            base[(size_t)c * stride] = run;
            run += tmp[c];
        }
    }
    if (tid < NSEQ * D2) {
        int s = tid / D2;
        int e = tid % D2;
        float* b2 = g_ksum + (size_t)s * NC * D2 + e;
        float tmp[NC];
#pragma unroll
        for (int c = 0; c < NC; c++) tmp[c] = b2[c * D2];
        float run = 0.f;
#pragma unroll
        for (int c = 0; c < NC; c++) {
            b2[c * D2] = run;
            run += tmp[c];
        }
    }
}

// ---------------------------------------------------------------------------
// Kernel 3: per-chunk output via tensor cores. grid = NSEQ*NC, 256 threads.
// Phase A: A[64(l) x 64(j)] = q~ @ k~^T (K=128), causal mask, store to smem.
// Phase B: out[64 x 64] = q~ @ S0 (K=128) + A @ v (K=64); divide by denom.
// smem floats:
//   qs [64][132]  (q~ tf32)                  132 % 32 == 4
//   u:  union( k~s [64][132], S0 [128][72] ) 9216 floats
//   vs [64][72]   (v tf32)                    72 % 32 == 8
//   As [64][68]   (masked A)                  68 % 32 == 4
//   ksum[128], den[64]
// ---------------------------------------------------------------------------
#define QS3 132
#define US3 132
#define S0S 72
#define VS3 72
#define AS3 68
#define K3_U_FLOATS 9216   /* max(64*132=8448, 128*72=9216) */
#define K3_SMEM_FLOATS (64*QS3 + K3_U_FLOATS + 64*VS3 + 64*AS3 + 128 + 64)
#define K3_SMEM (K3_SMEM_FLOATS * sizeof(float))

__global__ void k_output(const float* __restrict__ qg_,
                         const float* __restrict__ kg_,
                         const float* __restrict__ vg_,
                         float* __restrict__ outg) {
    extern __shared__ float sm[];
    float* qs    = sm;
    float* u     = qs + 64 * QS3;        // k~s then S0
    float* vs    = u + K3_U_FLOATS;
    float* As    = vs + 64 * VS3;
    float* ksum  = As + 64 * AS3;
    float* den   = ksum + 128;

    const int s = blockIdx.x >> 4;
    const int c = blockIdx.x & 15;
    const int t = threadIdx.x;

    const float* qg = qg_ + (size_t)(s * LSEQ + c * CHK) * DIM;
    const float* kg = kg_ + (size_t)(s * LSEQ + c * CHK) * DIM;
    const float* vg = vg_ + (size_t)(s * LSEQ + c * CHK) * DIM;

    for (int i = t; i < CHK * DIM / 4; i += 256) {
        int j = i >> 4;
        int d = (i & 15) * 4;
        float4 q4 = reinterpret_cast<const float4*>(qg)[i];
        float4 k4 = reinterpret_cast<const float4*>(kg)[i];
        float4 v4 = reinterpret_cast<const float4*>(vg)[i];
        int gl = c * CHK + j;
        float w = 1.5707963267948966f * (float)(gl + 1) * (1.0f / (float)LSEQ);
        float sw, cw;
        sincosf(w, &sw, &cw);
        float qx = fmaxf(q4.x, 0.f), qy = fmaxf(q4.y, 0.f);
        float qz = fmaxf(q4.z, 0.f), qw = fmaxf(q4.w, 0.f);
        float kx = fmaxf(k4.x, 0.f), ky = fmaxf(k4.y, 0.f);
        float kz = fmaxf(k4.z, 0.f), kw = fmaxf(k4.w, 0.f);
        *reinterpret_cast<float4*>(qs + j * QS3 + d) =
            make_float4(f2tf(qx * sw), f2tf(qy * sw), f2tf(qz * sw), f2tf(qw * sw));
        *reinterpret_cast<float4*>(qs + j * QS3 + 64 + d) =
            make_float4(f2tf(qx * cw), f2tf(qy * cw), f2tf(qz * cw), f2tf(qw * cw));
        *reinterpret_cast<float4*>(u + j * US3 + d) =
            make_float4(f2tf(kx * sw), f2tf(ky * sw), f2tf(kz * sw), f2tf(kw * sw));
        *reinterpret_cast<float4*>(u + j * US3 + 64 + d) =
            make_float4(f2tf(kx * cw), f2tf(ky * cw), f2tf(kz * cw), f2tf(kw * cw));
        *reinterpret_cast<float4*>(vs + j * VS3 + d) =
            make_float4(f2tf(v4.x), f2tf(v4.y), f2tf(v4.z), f2tf(v4.w));
    }
    if (t < D2) ksum[t] = g_ksum[(size_t)(s * NC + c) * D2 + t];
    __syncthreads();

    const int wid  = t >> 5;
    const int lane = t & 31;
    const int g    = lane >> 2;
    const int tig  = lane & 3;
    const int warpM = (wid >> 1) * 16;   // 0,16,32,48
    const int warpN = (wid & 1) * 32;    // 0,32

    // ---- Phase A: A = q~ @ k~^T, K=128, warp tile 16x32 ----
    {
        float acc[4][4];
#pragma unroll
        for (int nt = 0; nt < 4; nt++)
#pragma unroll
            for (int cc = 0; cc < 4; cc++) acc[nt][cc] = 0.f;

#pragma unroll
        for (int kk = 0; kk < 16; kk++) {
            const int k0 = kk * 8;
            uint32_t af[4];
            af[0] = BITS(qs[(warpM + g)     * QS3 + k0 + tig]);
            af[1] = BITS(qs[(warpM + g + 8) * QS3 + k0 + tig]);
            af[2] = BITS(qs[(warpM + g)     * QS3 + k0 + tig + 4]);
            af[3] = BITS(qs[(warpM + g + 8) * QS3 + k0 + tig + 4]);
            uint32_t bf[4][2];
#pragma unroll
            for (int nt = 0; nt < 4; nt++) {
                int nb = warpN + nt * 8 + g;
                bf[nt][0] = BITS(u[nb * US3 + k0 + tig]);
                bf[nt][1] = BITS(u[nb * US3 + k0 + tig + 4]);
            }
#pragma unroll
            for (int nt = 0; nt < 4; nt++)
                mma_tf32(acc[nt], af, bf[nt], acc[nt]);
        }
        // Causal mask + store (tf32-rounded so GEMM2 A-operand is clean).
#pragma unroll
        for (int nt = 0; nt < 4; nt++) {
#pragma unroll
            for (int cc = 0; cc < 4; cc++) {
                int l  = warpM + g + ((cc >= 2) ? 8 : 0);
                int jc = warpN + nt * 8 + 2 * tig + (cc & 1);
                As[l * AS3 + jc] = (jc <= l) ? f2tf(acc[nt][cc]) : 0.f;
            }
        }
    }
    __syncthreads();

    // ---- Load exclusive-prefix state S0 [128][72] over k~s region ----
    {
        const float* kvg = g_kv + (size_t)(s * NC + c) * D2 * DIM;
        for (int i = t; i < D2 * DIM / 4; i += 256) {
            int r = i >> 4;
            int d = (i & 15) * 4;
            float4 f4 = reinterpret_cast<const float4*>(kvg)[i];
            *reinterpret_cast<float4*>(u + r * S0S + d) =
                make_float4(f2tf(f4.x), f2tf(f4.y), f2tf(f4.z), f2tf(f4.w));
        }
    }
    __syncthreads();

    // Denominators.
    if (t < CHK) {
        int l = t;
        float d1 = 0.f;
        for (int kk = 0; kk < D2; kk++) d1 += qs[l * QS3 + kk] * ksum[kk];
        float d2v = 0.f;
        for (int jc = 0; jc <= l; jc++) d2v += As[l * AS3 + jc];
        den[l] = fmaxf(d1 + d2v, 1e-6f);
    }

    // ---- Phase B: out = q~ @ S0 (K=128) + A @ v (K=64) ----
    float acc2[4][4];
#pragma unroll
    for (int nt = 0; nt < 4; nt++)
#pragma unroll
        for (int cc = 0; cc < 4; cc++) acc2[nt][cc] = 0.f;

#pragma unroll
    for (int kk = 0; kk < 16; kk++) {
        const int k0 = kk * 8;
        uint32_t af[4];
        af[0] = BITS(qs[(warpM + g)     * QS3 + k0 + tig]);
        af[1] = BITS(qs[(warpM + g + 8) * QS3 + k0 + tig]);
        af[2] = BITS(qs[(warpM + g)     * QS3 + k0 + tig + 4]);
        af[3] = BITS(qs[(warpM + g + 8) * QS3 + k0 + tig + 4]);
        uint32_t bf[4][2];
#pragma unroll
        for (int nt = 0; nt < 4; nt++) {
            int nb = warpN + nt * 8 + g;
            bf[nt][0] = BITS(u[(k0 + tig)     * S0S + nb]);
            bf[nt][1] = BITS(u[(k0 + tig + 4) * S0S + nb]);
        }
#pragma unroll
        for (int nt = 0; nt < 4; nt++)
            mma_tf32(acc2[nt], af, bf[nt], acc2[nt]);
    }
#pragma unroll
    for (int kk = 0; kk < 8; kk++) {
        const int k0 = kk * 8;
        uint32_t af[4];
        af[0] = BITS(As[(warpM + g)     * AS3 + k0 + tig]);
        af[1] = BITS(As[(warpM + g + 8) * AS3 + k0 + tig]);
        af[2] = BITS(As[(warpM + g)     * AS3 + k0 + tig + 4]);
        af[3] = BITS(As[(warpM + g + 8) * AS3 + k0 + tig + 4]);
        uint32_t bf[4][2];
#pragma unroll
        for (int nt = 0; nt < 4; nt++) {
            int nb = warpN + nt * 8 + g;
            bf[nt][0] = BITS(vs[(k0 + tig)     * VS3 + nb]);
            bf[nt][1] = BITS(vs[(k0 + tig + 4) * VS3 + nb]);
        }
#pragma unroll
        for (int nt = 0; nt < 4; nt++)
            mma_tf32(acc2[nt], af, bf[nt], acc2[nt]);
    }
    __syncthreads();   // den ready for all threads

    // Epilogue: divide by denom and store.
    float* outp = outg + (size_t)(s * LSEQ + c * CHK) * DIM;
    {
        int l0 = warpM + g;
        int l1 = l0 + 8;
        float inv0 = 1.0f / den[l0];
        float inv1 = 1.0f / den[l1];
#pragma unroll
        for (int nt = 0; nt < 4; nt++) {
            int n0 = warpN + nt * 8 + 2 * tig;
            *reinterpret_cast<float2*>(outp + l0 * DIM + n0) =
                make_float2(acc2[nt][0] * inv0, acc2[nt][1] * inv0);
            *reinterpret_cast<float2*>(outp + l1 * DIM + n0) =
                make_float2(acc2[nt][2] * inv1, acc2[nt][3] * inv1);
        }
    }
}

// ---------------------------------------------------------------------------
extern "C" void kernel_launch(void* const* d_in, const int* in_sizes, int n_in,
                              void* d_out, int out_size) {
    const float* q = (const float*)d_in[0];
    const float* k = (const float*)d_in[1];
    const float* v = (const float*)d_in[2];
    float* out = (float*)d_out;

    static bool attr_set = false;
    if (!attr_set) {
        cudaFuncSetAttribute(k_chunksum,
                             cudaFuncAttributeMaxDynamicSharedMemorySize, K1_SMEM);
        cudaFuncSetAttribute(k_output,
                             cudaFuncAttributeMaxDynamicSharedMemorySize, K3_SMEM);
        attr_set = true;
    }

    k_chunksum<<<NSEQ * NC, 256, K1_SMEM>>>(k, v);
    int scan_threads = NSEQ * D2 * DIM;                     // 131072
    k_scan<<<(scan_threads + 255) / 256, 256>>>();
    k_output<<<NSEQ * NC, 256, K3_SMEM>>>(q, k, v, out);
}